// round 2
// baseline (speedup 1.0000x reference)
#include <cuda_runtime.h>
#include <cstdint>

#define BB 512
#define CC 256
#define HH 1024
#define NCB 500000

// ---------------- scratch (static device globals; no allocation) -------------
__device__ unsigned long long g_best[BB];
__device__ float g_prev[BB * CC];
__device__ float g_bi [BB * HH];
__device__ float g_h1 [BB * HH];
__device__ float g_s2 [BB * HH];
__device__ float g_s3 [BB * HH];
__device__ float g_h2 [BB * HH];
__device__ float g_out[BB * HH];

// ---------------- helpers ----------------------------------------------------
__device__ __forceinline__ unsigned long long ffma2(unsigned long long a,
                                                    unsigned long long b,
                                                    unsigned long long c) {
    unsigned long long d;
    asm("fma.rn.f32x2 %0, %1, %2, %3;" : "=l"(d) : "l"(a), "l"(b), "l"(c));
    return d;
}
union U2F { unsigned long long u; float2 f; };
__device__ __forceinline__ float2 u2f2(unsigned long long u) { U2F c; c.u = u; return c.f; }
// monotonic float -> uint mapping (order preserving)
__device__ __forceinline__ unsigned int fmono(float f) {
    unsigned int u = __float_as_uint(f);
    return (u & 0x80000000u) ? ~u : (u | 0x80000000u);
}

// ---------------- init -------------------------------------------------------
__global__ void init_kernel() {
    int t = threadIdx.x;
    if (t < BB) g_best[t] = ~0ull;
}

// ---------------- argmin distance search -------------------------------------
// Per block: 128 codebook rows, full K=256 resident in smem (swizzled k-major).
// Loop over 4 batch tiles of 128 codes. 256 threads, 8x8 micro-tile, FFMA2.
#define SRCH_SMEM_FLOATS (256*128 + 16*128*2 + 128)

__global__ void __launch_bounds__(256, 1)
search_kernel(const float* __restrict__ codes, const float* __restrict__ codebook) {
    extern __shared__ __align__(16) float sm[];
    float* Bs    = sm;                       // k-major [256][128], float4-col swizzle
    float* As2f  = sm + 256 * 128;           // replicated float2 [16][128]
    float* norms = As2f + 16 * 128 * 2;      // [128] logical-n norms

    const int tid = threadIdx.x;
    const int n0  = blockIdx.x * 128;

    // ---- load codebook tile, transposed to k-major with XOR swizzle ----
    // idx -> n_local = idx>>6 (row), kq = idx&63 (float4 along K)
    #pragma unroll 4
    for (int it = 0; it < 32; ++it) {
        int idx = tid + it * 256;
        int nl  = idx >> 6;
        int kq  = idx & 63;
        int n   = n0 + nl;
        float4 v = make_float4(0.f, 0.f, 0.f, 0.f);
        if (n < NCB) v = reinterpret_cast<const float4*>(codebook)[n * 64 + kq];
        int n4 = nl >> 2, nr = nl & 3;
        int col4 = n4 ^ (kq & 31);           // read-time s = (k>>2)&31 = kq&31
        float* base = Bs + (4 * kq) * 128 + col4 * 4 + nr;
        base[0]   = v.x;
        base[128] = v.y;
        base[256] = v.z;
        base[384] = v.w;
    }
    __syncthreads();

    // ---- codebook norms (logical index) ----
    if (tid < 128) {
        int n = n0 + tid;
        if (n < NCB) {
            int n4 = tid >> 2, nr = tid & 3;
            float acc = 0.f;
            for (int kq = 0; kq < 64; ++kq) {
                int col4 = n4 ^ (kq & 31);
                const float* b = Bs + (4 * kq) * 128 + col4 * 4 + nr;
                acc += b[0] * b[0] + b[128] * b[128] + b[256] * b[256] + b[384] * b[384];
            }
            norms[tid] = acc;
        } else {
            norms[tid] = __int_as_float(0x7f800000);  // +inf -> never selected
        }
    }

    const int tn = tid & 15;   // codebook-dim thread coord (n = 8*tn .. 8*tn+7)
    const int tm = tid >> 4;   // batch-dim thread coord    (m = 8*tm .. 8*tm+7)

    for (int bt = 0; bt < 4; ++bt) {
        unsigned long long c2[8][4];
        #pragma unroll
        for (int i = 0; i < 8; ++i)
            #pragma unroll
            for (int j = 0; j < 4; ++j) c2[i][j] = 0ull;

        for (int kb = 0; kb < 256; kb += 16) {
            __syncthreads();
            // load codes chunk: 128 rows x 16 k, replicated (a,a) pairs
            #pragma unroll
            for (int it = 0; it < 2; ++it) {
                int idx = tid + it * 256;
                int m = idx >> 2, kq = idx & 3;
                float4 v = reinterpret_cast<const float4*>(codes)
                               [(bt * 128 + m) * 64 + (kb >> 2) + kq];
                float2* a = reinterpret_cast<float2*>(As2f) + (4 * kq) * 128 + m;
                a[0]       = make_float2(v.x, v.x);
                a[128]     = make_float2(v.y, v.y);
                a[256]     = make_float2(v.z, v.z);
                a[384]     = make_float2(v.w, v.w);
            }
            __syncthreads();

            #pragma unroll
            for (int kk = 0; kk < 16; ++kk) {
                int k = kb + kk;
                int s = (k >> 2) & 31;
                const ulonglong2* Brow =
                    reinterpret_cast<const ulonglong2*>(Bs + k * 128);
                ulonglong2 bA = Brow[(2 * tn) ^ s];
                ulonglong2 bB = Brow[(2 * tn + 1) ^ s];
                const unsigned long long* A =
                    reinterpret_cast<const unsigned long long*>(As2f) + kk * 128 + 8 * tm;
                ulonglong2 a01 = *reinterpret_cast<const ulonglong2*>(A + 0);
                ulonglong2 a23 = *reinterpret_cast<const ulonglong2*>(A + 2);
                ulonglong2 a45 = *reinterpret_cast<const ulonglong2*>(A + 4);
                ulonglong2 a67 = *reinterpret_cast<const ulonglong2*>(A + 6);
                unsigned long long av[8] = {a01.x, a01.y, a23.x, a23.y,
                                            a45.x, a45.y, a67.x, a67.y};
                #pragma unroll
                for (int i = 0; i < 8; ++i) {
                    c2[i][0] = ffma2(av[i], bA.x, c2[i][0]);
                    c2[i][1] = ffma2(av[i], bA.y, c2[i][1]);
                    c2[i][2] = ffma2(av[i], bB.x, c2[i][2]);
                    c2[i][3] = ffma2(av[i], bB.y, c2[i][3]);
                }
            }
        }

        // ---- epilogue: s = ||c||^2 - 2*dot, min-reduce, global atomicMin ----
        #pragma unroll
        for (int i = 0; i < 8; ++i) {
            float bs = __int_as_float(0x7f800000);
            int   bn = 0;
            #pragma unroll
            for (int j = 0; j < 4; ++j) {
                float2 p = u2f2(c2[i][j]);
                int na = 8 * tn + 2 * j;
                float sa = norms[na]     - 2.0f * p.x;
                float sb = norms[na + 1] - 2.0f * p.y;
                if (sa < bs) { bs = sa; bn = na; }
                if (sb < bs) { bs = sb; bn = na + 1; }
            }
            unsigned long long key =
                ((unsigned long long)fmono(bs) << 32) | (unsigned int)(n0 + bn);
            #pragma unroll
            for (int off = 8; off > 0; off >>= 1) {
                unsigned long long o = __shfl_down_sync(0xffffffffu, key, off, 16);
                if (o < key) key = o;
            }
            if (tn == 0) {
                int m = bt * 128 + tm * 8 + i;
                atomicMin(&g_best[m], key);
            }
        }
    }
}

// ---------------- gather prev = codebook[nbr] --------------------------------
__global__ void gather_kernel(const float* __restrict__ codebook) {
    int b = blockIdx.x;
    unsigned int n = (unsigned int)(g_best[b] & 0xFFFFFFFFull);
    reinterpret_cast<float4*>(g_prev)[b * 64 + threadIdx.x] =
        reinterpret_cast<const float4*>(codebook)[(size_t)n * 64 + threadIdx.x];
}

// ---------------- generic NT GEMM: Y = act((X1[+X2]) @ W^T + b) --------------
// M=512 rows, tiles 64x64, 256 threads, 4x4 micro via FFMA2.
// flags: bit0 = tanh, bit1 = accumulate into Y
__global__ void __launch_bounds__(256)
gemm_nt(const float* __restrict__ X1, const float* __restrict__ X2,
        const float* __restrict__ W,  const float* __restrict__ bias,
        float* __restrict__ Y, int Kd, int Nd, int flags) {
    __shared__ __align__(16) float2 As2[16 * 64];  // [k][m] replicated
    __shared__ __align__(16) float  Bs [16 * 64];  // [k][n] swizzled (col4 = n4 ^ kq)

    const int tid = threadIdx.x;
    const int tn  = tid & 15;
    const int tm  = tid >> 4;
    const int m0  = blockIdx.y * 64;
    const int n0  = blockIdx.x * 64;
    const int K4  = Kd >> 2;

    unsigned long long c2[4][2];
    #pragma unroll
    for (int i = 0; i < 4; ++i) { c2[i][0] = 0ull; c2[i][1] = 0ull; }

    for (int kb = 0; kb < Kd; kb += 16) {
        __syncthreads();
        {   // A: 64 rows x 4 float4 (one per thread), optional pre-add X2
            int m = tid >> 2, kq = tid & 3;
            int gk = (kb >> 2) + kq;
            float4 v = reinterpret_cast<const float4*>(X1)[(m0 + m) * K4 + gk];
            if (X2) {
                float4 w = reinterpret_cast<const float4*>(X2)[(m0 + m) * K4 + gk];
                v.x += w.x; v.y += w.y; v.z += w.z; v.w += w.w;
            }
            float2* a = As2 + (4 * kq) * 64 + m;
            a[0]   = make_float2(v.x, v.x);
            a[64]  = make_float2(v.y, v.y);
            a[128] = make_float2(v.z, v.z);
            a[192] = make_float2(v.w, v.w);
        }
        {   // B: 64 rows x 4 float4, swizzled store
            int n = tid >> 2, kq = tid & 3;
            float4 v = reinterpret_cast<const float4*>(W)[(n0 + n) * K4 + (kb >> 2) + kq];
            int n4 = n >> 2, nr = n & 3;
            int col4 = n4 ^ kq;
            float* b = Bs + (4 * kq) * 64 + col4 * 4 + nr;
            b[0] = v.x; b[64] = v.y; b[128] = v.z; b[192] = v.w;
        }
        __syncthreads();

        #pragma unroll
        for (int kk = 0; kk < 16; ++kk) {
            const unsigned long long* A =
                reinterpret_cast<const unsigned long long*>(As2) + kk * 64 + 4 * tm;
            ulonglong2 aA = *reinterpret_cast<const ulonglong2*>(A + 0);
            ulonglong2 aB = *reinterpret_cast<const ulonglong2*>(A + 2);
            int col4 = tn ^ (kk >> 2);
            ulonglong2 b = *reinterpret_cast<const ulonglong2*>(Bs + kk * 64 + col4 * 4);
            c2[0][0] = ffma2(aA.x, b.x, c2[0][0]); c2[0][1] = ffma2(aA.x, b.y, c2[0][1]);
            c2[1][0] = ffma2(aA.y, b.x, c2[1][0]); c2[1][1] = ffma2(aA.y, b.y, c2[1][1]);
            c2[2][0] = ffma2(aB.x, b.x, c2[2][0]); c2[2][1] = ffma2(aB.x, b.y, c2[2][1]);
            c2[3][0] = ffma2(aB.y, b.x, c2[3][0]); c2[3][1] = ffma2(aB.y, b.y, c2[3][1]);
        }
    }

    const int nb = n0 + 4 * tn;
    float b0 = bias[nb], b1 = bias[nb + 1], b2v = bias[nb + 2], b3 = bias[nb + 3];
    #pragma unroll
    for (int i = 0; i < 4; ++i) {
        int m = m0 + 4 * tm + i;
        float2 p0 = u2f2(c2[i][0]);
        float2 p1 = u2f2(c2[i][1]);
        float v0 = p0.x + b0, v1 = p0.y + b1, v2 = p1.x + b2v, v3 = p1.y + b3;
        if (flags & 1) { v0 = tanhf(v0); v1 = tanhf(v1); v2 = tanhf(v2); v3 = tanhf(v3); }
        float* yr = Y + (size_t)m * Nd + nb;
        if (flags & 2) {
            yr[0] += v0; yr[1] += v1; yr[2] += v2; yr[3] += v3;
        } else {
            *reinterpret_cast<float4*>(yr) = make_float4(v0, v1, v2, v3);
        }
    }
}

// ---------------- launch -----------------------------------------------------
extern "C" void kernel_launch(void* const* d_in, const int* in_sizes, int n_in,
                              void* d_out, int out_size) {
    const float* codes    = (const float*)d_in[0];
    const float* codebook = (const float*)d_in[1];
    const float* w_in  = (const float*)d_in[2],  *b_in  = (const float*)d_in[3];
    const float* w_h1  = (const float*)d_in[4],  *b_h1  = (const float*)d_in[5];
    const float* w_s2  = (const float*)d_in[6],  *b_s2  = (const float*)d_in[7];
    const float* w_s3  = (const float*)d_in[8],  *b_s3  = (const float*)d_in[9];
    const float* w_h2  = (const float*)d_in[10], *b_h2  = (const float*)d_in[11];
    const float* w_s1o = (const float*)d_in[12], *b_s1o = (const float*)d_in[13];
    const float* w_s2o = (const float*)d_in[14], *b_s2o = (const float*)d_in[15];
    const float* w_h3  = (const float*)d_in[16], *b_h3  = (const float*)d_in[17];
    const float* w_mu  = (const float*)d_in[18], *b_mu  = (const float*)d_in[19];
    const float* w_s   = (const float*)d_in[20], *b_s   = (const float*)d_in[21];

    float* out_mu = (float*)d_out;
    float* out_ls = (float*)d_out + BB * CC;

    // resolve scratch device-global addresses
    float *p_prev, *p_bi, *p_h1, *p_s2, *p_s3, *p_h2, *p_out;
    cudaGetSymbolAddress((void**)&p_prev, g_prev);
    cudaGetSymbolAddress((void**)&p_bi,  g_bi);
    cudaGetSymbolAddress((void**)&p_h1,  g_h1);
    cudaGetSymbolAddress((void**)&p_s2,  g_s2);
    cudaGetSymbolAddress((void**)&p_s3,  g_s3);
    cudaGetSymbolAddress((void**)&p_h2,  g_h2);
    cudaGetSymbolAddress((void**)&p_out, g_out);

    size_t srch_smem = (size_t)SRCH_SMEM_FLOATS * sizeof(float);
    cudaFuncSetAttribute(search_kernel,
                         cudaFuncAttributeMaxDynamicSharedMemorySize, (int)srch_smem);

    init_kernel<<<1, 512>>>();
    int nblocks = (NCB + 127) / 128;
    search_kernel<<<nblocks, 256, srch_smem>>>(codes, codebook);
    gather_kernel<<<BB, 64>>>(codebook);

    dim3 blk(256);
    dim3 gridH(HH / 64, BB / 64);   // N=1024
    dim3 gridC(CC / 64, BB / 64);   // N=256

    // i  = tanh(prev @ w_in^T + b_in)
    gemm_nt<<<gridH, blk>>>(p_prev, nullptr, w_in, b_in, p_bi, CC, HH, 1);
    // h1 = tanh(i @ w_h1^T + b_h1)
    gemm_nt<<<gridH, blk>>>(p_bi, nullptr, w_h1, b_h1, p_h1, HH, HH, 1);
    // s2 = tanh(h1 @ w_s2^T + b_s2)
    gemm_nt<<<gridH, blk>>>(p_h1, nullptr, w_s2, b_s2, p_s2, HH, HH, 1);
    // s3 = tanh(h1 @ w_s3^T + b_s3)
    gemm_nt<<<gridH, blk>>>(p_h1, nullptr, w_s3, b_s3, p_s3, HH, HH, 1);
    // h2 = tanh((h1+s2) @ w_h2^T + b_h2)
    gemm_nt<<<gridH, blk>>>(p_h1, p_s2, w_h2, b_h2, p_h2, HH, HH, 1);
    // out  = tanh(h1 @ w_s1o^T + b_s1o)           (o1)
    gemm_nt<<<gridH, blk>>>(p_h1, nullptr, w_s1o, b_s1o, p_out, HH, HH, 1);
    // out += tanh(h2 @ w_s2o^T + b_s2o)           (o2)
    gemm_nt<<<gridH, blk>>>(p_h2, nullptr, w_s2o, b_s2o, p_out, HH, HH, 3);
    // out += tanh((h2+s3) @ w_h3^T + b_h3)        (o3)
    gemm_nt<<<gridH, blk>>>(p_h2, p_s3, w_h3, b_h3, p_out, HH, HH, 3);
    // mu     = out @ w_mu^T + b_mu
    gemm_nt<<<gridC, blk>>>(p_out, nullptr, w_mu, b_mu, out_mu, HH, CC, 0);
    // logstd = out @ w_s^T + b_s
    gemm_nt<<<gridC, blk>>>(p_out, nullptr, w_s, b_s, out_ls, HH, CC, 0);
}

// round 6
// speedup vs baseline: 1.1170x; 1.1170x over previous
#include <cuda_runtime.h>
#include <cstdint>

#define BB 512
#define CC 256
#define HH 1024
#define NCB 500000

// ---------------- scratch (static device globals; no allocation) -------------
__device__ unsigned long long g_best[BB];
__device__ float g_prev[BB * CC];
__device__ float g_bi [BB * HH];
__device__ float g_h1 [BB * HH];
__device__ float g_s2 [BB * HH];
__device__ float g_s3 [BB * HH];
__device__ float g_h2 [BB * HH];
__device__ float g_out[BB * HH];

// ---------------- helpers ----------------------------------------------------
__device__ __forceinline__ unsigned long long ffma2(unsigned long long a,
                                                    unsigned long long b,
                                                    unsigned long long c) {
    unsigned long long d;
    asm("fma.rn.f32x2 %0, %1, %2, %3;" : "=l"(d) : "l"(a), "l"(b), "l"(c));
    return d;
}
union U2F { unsigned long long u; float2 f; };
__device__ __forceinline__ float2 u2f2(unsigned long long u) { U2F c; c.u = u; return c.f; }
// monotonic float -> uint mapping (order preserving)
__device__ __forceinline__ unsigned int fmono(float f) {
    unsigned int u = __float_as_uint(f);
    return (u & 0x80000000u) ? ~u : (u | 0x80000000u);
}
__device__ __forceinline__ void bar_group(int id) {
    asm volatile("bar.sync %0, 256;" :: "r"(id) : "memory");
}

// ---------------- init -------------------------------------------------------
__global__ void init_kernel() {
    int t = threadIdx.x;
    if (t < BB) g_best[t] = ~0ull;
}

// ---------------- argmin distance search -------------------------------------
// Per block: 128 codebook rows, full K=256 resident in smem (swizzled k-major).
// 512 threads = 2 groups of 256; each group owns 2 of the 4 batch tiles and a
// private A-staging buffer + private named barrier. 8x8 micro-tile, FFMA2.
#define SRCH_SMEM_FLOATS (256*128 + 2*16*128*2 + 128)

__global__ void __launch_bounds__(512, 1)
search_kernel(const float* __restrict__ codes, const float* __restrict__ codebook) {
    extern __shared__ __align__(16) float sm[];
    float* Bs    = sm;                             // k-major [256][128], float4-col swizzle
    float* As2f  = sm + 256 * 128;                 // 2 x replicated float2 [16][128]
    float* norms = As2f + 2 * 16 * 128 * 2;        // [128] logical-n norms

    const int tid  = threadIdx.x;
    const int g    = tid >> 8;                     // group 0/1
    const int tid2 = tid & 255;
    const int n0   = blockIdx.x * 128;

    // ---- load codebook tile, transposed to k-major with XOR swizzle ----
    #pragma unroll 4
    for (int it = 0; it < 16; ++it) {
        int idx = tid + it * 512;
        int nl  = idx >> 6;
        int kq  = idx & 63;
        int n   = n0 + nl;
        float4 v = make_float4(0.f, 0.f, 0.f, 0.f);
        if (n < NCB) v = reinterpret_cast<const float4*>(codebook)[n * 64 + kq];
        int n4 = nl >> 2, nr = nl & 3;
        int col4 = n4 ^ (kq & 31);                 // read-time s = (k>>2)&31 = kq&31
        float* base = Bs + (4 * kq) * 128 + col4 * 4 + nr;
        base[0]   = v.x;
        base[128] = v.y;
        base[256] = v.z;
        base[384] = v.w;
    }
    __syncthreads();

    // ---- codebook norms (logical index) ----
    if (tid < 128) {
        int n = n0 + tid;
        if (n < NCB) {
            int n4 = tid >> 2, nr = tid & 3;
            float acc = 0.f;
            for (int kq = 0; kq < 64; ++kq) {
                int col4 = n4 ^ (kq & 31);
                const float* b = Bs + (4 * kq) * 128 + col4 * 4 + nr;
                acc += b[0] * b[0] + b[128] * b[128] + b[256] * b[256] + b[384] * b[384];
            }
            norms[tid] = acc;
        } else {
            norms[tid] = __int_as_float(0x7f800000);  // +inf -> never selected
        }
    }
    __syncthreads();

    const int tn = tid2 & 15;   // codebook-dim coord (n = 8*tn .. 8*tn+7)
    const int tm = tid2 >> 4;   // batch-dim coord    (m = 8*tm .. 8*tm+7)
    float2* Ag = reinterpret_cast<float2*>(As2f) + g * (16 * 128);
    const int bar_id = g + 1;

    for (int bt = 0; bt < 2; ++bt) {
        const int tile = 2 * bt + g;               // batch tile 0..3

        unsigned long long c2[8][4];
        #pragma unroll
        for (int i = 0; i < 8; ++i)
            #pragma unroll
            for (int j = 0; j < 4; ++j) c2[i][j] = 0ull;

        for (int kb = 0; kb < 256; kb += 16) {
            bar_group(bar_id);
            // stage codes chunk: 128 rows x 16 k, replicated (a,a) pairs
            #pragma unroll
            for (int it = 0; it < 2; ++it) {
                int idx = tid2 + it * 256;
                int m = idx >> 2, kq = idx & 3;
                float4 v = reinterpret_cast<const float4*>(codes)
                               [(tile * 128 + m) * 64 + (kb >> 2) + kq];
                float2* a = Ag + (4 * kq) * 128 + m;
                a[0]   = make_float2(v.x, v.x);
                a[128] = make_float2(v.y, v.y);
                a[256] = make_float2(v.z, v.z);
                a[384] = make_float2(v.w, v.w);
            }
            bar_group(bar_id);

            #pragma unroll
            for (int kk = 0; kk < 16; ++kk) {
                int k = kb + kk;
                int s = (k >> 2) & 31;
                const ulonglong2* Brow =
                    reinterpret_cast<const ulonglong2*>(Bs + k * 128);
                ulonglong2 bA = Brow[(2 * tn) ^ s];
                ulonglong2 bB = Brow[(2 * tn + 1) ^ s];
                const unsigned long long* A =
                    reinterpret_cast<const unsigned long long*>(Ag) + kk * 128 + 8 * tm;
                ulonglong2 a01 = *reinterpret_cast<const ulonglong2*>(A + 0);
                ulonglong2 a23 = *reinterpret_cast<const ulonglong2*>(A + 2);
                ulonglong2 a45 = *reinterpret_cast<const ulonglong2*>(A + 4);
                ulonglong2 a67 = *reinterpret_cast<const ulonglong2*>(A + 6);
                unsigned long long av[8] = {a01.x, a01.y, a23.x, a23.y,
                                            a45.x, a45.y, a67.x, a67.y};
                #pragma unroll
                for (int i = 0; i < 8; ++i) {
                    c2[i][0] = ffma2(av[i], bA.x, c2[i][0]);
                    c2[i][1] = ffma2(av[i], bA.y, c2[i][1]);
                    c2[i][2] = ffma2(av[i], bB.x, c2[i][2]);
                    c2[i][3] = ffma2(av[i], bB.y, c2[i][3]);
                }
            }
        }

        // ---- epilogue: s = ||c||^2 - 2*dot, min-reduce, global atomicMin ----
        #pragma unroll
        for (int i = 0; i < 8; ++i) {
            float bs = __int_as_float(0x7f800000);
            int   bn = 0;
            #pragma unroll
            for (int j = 0; j < 4; ++j) {
                float2 p = u2f2(c2[i][j]);
                int na = 8 * tn + 2 * j;
                float sa = norms[na]     - 2.0f * p.x;
                float sb = norms[na + 1] - 2.0f * p.y;
                if (sa < bs) { bs = sa; bn = na; }
                if (sb < bs) { bs = sb; bn = na + 1; }
            }
            unsigned long long key =
                ((unsigned long long)fmono(bs) << 32) | (unsigned int)(n0 + bn);
            #pragma unroll
            for (int off = 8; off > 0; off >>= 1) {
                unsigned long long o = __shfl_down_sync(0xffffffffu, key, off, 16);
                if (o < key) key = o;
            }
            if (tn == 0) {
                int m = tile * 128 + tm * 8 + i;
                atomicMin(&g_best[m], key);
            }
        }
    }
}

// ---------------- gather prev = codebook[nbr] --------------------------------
__global__ void gather_kernel(const float* __restrict__ codebook) {
    int b = blockIdx.x;
    unsigned int n = (unsigned int)(g_best[b] & 0xFFFFFFFFull);
    reinterpret_cast<float4*>(g_prev)[b * 64 + threadIdx.x] =
        reinterpret_cast<const float4*>(codebook)[(size_t)n * 64 + threadIdx.x];
}

// ---------------- generic NT GEMM core: Y = act((X1[+X2]) @ W^T + b) ---------
// M=512 rows, tiles 64x64, 256 threads, 4x4 micro via FFMA2.
// flags: bit0 = tanh, bit1 = accumulate into Y
__device__ __forceinline__
void gemm_core(const float* __restrict__ X1, const float* __restrict__ X2,
               const float* __restrict__ W,  const float* __restrict__ bias,
               float* __restrict__ Y, int Kd, int Nd, int flags,
               int m0, int n0) {
    __shared__ __align__(16) float2 As2[16 * 64];  // [k][m] replicated
    __shared__ __align__(16) float  Bs [16 * 64];  // [k][n] swizzled (col4 = n4 ^ kq)

    const int tid = threadIdx.x;
    const int tn  = tid & 15;
    const int tm  = tid >> 4;
    const int K4  = Kd >> 2;

    unsigned long long c2[4][2];
    #pragma unroll
    for (int i = 0; i < 4; ++i) { c2[i][0] = 0ull; c2[i][1] = 0ull; }

    for (int kb = 0; kb < Kd; kb += 16) {
        __syncthreads();
        {   // A: 64 rows x 4 float4 (one per thread), optional pre-add X2
            int m = tid >> 2, kq = tid & 3;
            int gk = (kb >> 2) + kq;
            float4 v = reinterpret_cast<const float4*>(X1)[(m0 + m) * K4 + gk];
            if (X2) {
                float4 w = reinterpret_cast<const float4*>(X2)[(m0 + m) * K4 + gk];
                v.x += w.x; v.y += w.y; v.z += w.z; v.w += w.w;
            }
            float2* a = As2 + (4 * kq) * 64 + m;
            a[0]   = make_float2(v.x, v.x);
            a[64]  = make_float2(v.y, v.y);
            a[128] = make_float2(v.z, v.z);
            a[192] = make_float2(v.w, v.w);
        }
        {   // B: 64 rows x 4 float4, swizzled store
            int n = tid >> 2, kq = tid & 3;
            float4 v = reinterpret_cast<const float4*>(W)[(n0 + n) * K4 + (kb >> 2) + kq];
            int n4 = n >> 2, nr = n & 3;
            int col4 = n4 ^ kq;
            float* b = Bs + (4 * kq) * 64 + col4 * 4 + nr;
            b[0] = v.x; b[64] = v.y; b[128] = v.z; b[192] = v.w;
        }
        __syncthreads();

        #pragma unroll
        for (int kk = 0; kk < 16; ++kk) {
            const unsigned long long* A =
                reinterpret_cast<const unsigned long long*>(As2) + kk * 64 + 4 * tm;
            ulonglong2 aA = *reinterpret_cast<const ulonglong2*>(A + 0);
            ulonglong2 aB = *reinterpret_cast<const ulonglong2*>(A + 2);
            int col4 = tn ^ (kk >> 2);
            ulonglong2 b = *reinterpret_cast<const ulonglong2*>(Bs + kk * 64 + col4 * 4);
            c2[0][0] = ffma2(aA.x, b.x, c2[0][0]); c2[0][1] = ffma2(aA.x, b.y, c2[0][1]);
            c2[1][0] = ffma2(aA.y, b.x, c2[1][0]); c2[1][1] = ffma2(aA.y, b.y, c2[1][1]);
            c2[2][0] = ffma2(aB.x, b.x, c2[2][0]); c2[2][1] = ffma2(aB.x, b.y, c2[2][1]);
            c2[3][0] = ffma2(aB.y, b.x, c2[3][0]); c2[3][1] = ffma2(aB.y, b.y, c2[3][1]);
        }
    }

    const int nb = n0 + 4 * tn;
    float b0 = bias[nb], b1 = bias[nb + 1], b2v = bias[nb + 2], b3 = bias[nb + 3];
    #pragma unroll
    for (int i = 0; i < 4; ++i) {
        int m = m0 + 4 * tm + i;
        float2 p0 = u2f2(c2[i][0]);
        float2 p1 = u2f2(c2[i][1]);
        float v0 = p0.x + b0, v1 = p0.y + b1, v2 = p1.x + b2v, v3 = p1.y + b3;
        if (flags & 1) { v0 = tanhf(v0); v1 = tanhf(v1); v2 = tanhf(v2); v3 = tanhf(v3); }
        float* yr = Y + (size_t)m * Nd + nb;
        if (flags & 2) {
            yr[0] += v0; yr[1] += v1; yr[2] += v2; yr[3] += v3;
        } else {
            *reinterpret_cast<float4*>(yr) = make_float4(v0, v1, v2, v3);
        }
    }
}

__global__ void __launch_bounds__(256)
gemm_nt(const float* __restrict__ X1, const float* __restrict__ X2,
        const float* __restrict__ W,  const float* __restrict__ bias,
        float* __restrict__ Y, int Kd, int Nd, int flags) {
    gemm_core(X1, X2, W, bias, Y, Kd, Nd, flags,
              blockIdx.y * 64, blockIdx.x * 64);
}

// Same X1, up to 3 (W, bias, Y) sets selected by blockIdx.z — fills the chip.
__global__ void __launch_bounds__(256)
gemm_nt_multi(const float* __restrict__ X1,
              const float* __restrict__ W0, const float* __restrict__ b0, float* __restrict__ Y0,
              const float* __restrict__ W1, const float* __restrict__ b1, float* __restrict__ Y1,
              const float* __restrict__ W2, const float* __restrict__ b2, float* __restrict__ Y2,
              int Kd, int Nd, int flags) {
    const float* W; const float* bias; float* Y;
    if (blockIdx.z == 0)      { W = W0; bias = b0; Y = Y0; }
    else if (blockIdx.z == 1) { W = W1; bias = b1; Y = Y1; }
    else                      { W = W2; bias = b2; Y = Y2; }
    gemm_core(X1, nullptr, W, bias, Y, Kd, Nd, flags,
              blockIdx.y * 64, blockIdx.x * 64);
}

// ---------------- launch -----------------------------------------------------
extern "C" void kernel_launch(void* const* d_in, const int* in_sizes, int n_in,
                              void* d_out, int out_size) {
    const float* codes    = (const float*)d_in[0];
    const float* codebook = (const float*)d_in[1];
    const float* w_in  = (const float*)d_in[2],  *b_in  = (const float*)d_in[3];
    const float* w_h1  = (const float*)d_in[4],  *b_h1  = (const float*)d_in[5];
    const float* w_s2  = (const float*)d_in[6],  *b_s2  = (const float*)d_in[7];
    const float* w_s3  = (const float*)d_in[8],  *b_s3  = (const float*)d_in[9];
    const float* w_h2  = (const float*)d_in[10], *b_h2  = (const float*)d_in[11];
    const float* w_s1o = (const float*)d_in[12], *b_s1o = (const float*)d_in[13];
    const float* w_s2o = (const float*)d_in[14], *b_s2o = (const float*)d_in[15];
    const float* w_h3  = (const float*)d_in[16], *b_h3  = (const float*)d_in[17];
    const float* w_mu  = (const float*)d_in[18], *b_mu  = (const float*)d_in[19];
    const float* w_s   = (const float*)d_in[20], *b_s   = (const float*)d_in[21];

    float* out_mu = (float*)d_out;
    float* out_ls = (float*)d_out + BB * CC;

    // resolve scratch device-global addresses
    float *p_prev, *p_bi, *p_h1, *p_s2, *p_s3, *p_h2, *p_out;
    cudaGetSymbolAddress((void**)&p_prev, g_prev);
    cudaGetSymbolAddress((void**)&p_bi,  g_bi);
    cudaGetSymbolAddress((void**)&p_h1,  g_h1);
    cudaGetSymbolAddress((void**)&p_s2,  g_s2);
    cudaGetSymbolAddress((void**)&p_s3,  g_s3);
    cudaGetSymbolAddress((void**)&p_h2,  g_h2);
    cudaGetSymbolAddress((void**)&p_out, g_out);

    size_t srch_smem = (size_t)SRCH_SMEM_FLOATS * sizeof(float);
    cudaFuncSetAttribute(search_kernel,
                         cudaFuncAttributeMaxDynamicSharedMemorySize, (int)srch_smem);

    init_kernel<<<1, 512>>>();
    int nblocks = (NCB + 127) / 128;
    search_kernel<<<nblocks, 512, srch_smem>>>(codes, codebook);
    gather_kernel<<<BB, 64>>>(codebook);

    dim3 blk(256);
    dim3 gridH(HH / 64, BB / 64);          // N=1024
    dim3 gridH3(HH / 64, BB / 64, 3);      // 3-way batched
    dim3 gridC2(CC / 64, BB / 64, 2);      // 2-way batched, N=256

    // i  = tanh(prev @ w_in^T + b_in)
    gemm_nt<<<gridH, blk>>>(p_prev, nullptr, w_in, b_in, p_bi, CC, HH, 1);
    // h1 = tanh(i @ w_h1^T + b_h1)
    gemm_nt<<<gridH, blk>>>(p_bi, nullptr, w_h1, b_h1, p_h1, HH, HH, 1);
    // s2 / s3 / o1(out) from h1, all tanh, one batched launch
    gemm_nt_multi<<<gridH3, blk>>>(p_h1,
                                   w_s2,  b_s2,  p_s2,
                                   w_s3,  b_s3,  p_s3,
                                   w_s1o, b_s1o, p_out,
                                   HH, HH, 1);
    // h2 = tanh((h1+s2) @ w_h2^T + b_h2)
    gemm_nt<<<gridH, blk>>>(p_h1, p_s2, w_h2, b_h2, p_h2, HH, HH, 1);
    // out += tanh(h2 @ w_s2o^T + b_s2o)           (o2)
    gemm_nt<<<gridH, blk>>>(p_h2, nullptr, w_s2o, b_s2o, p_out, HH, HH, 3);
    // out += tanh((h2+s3) @ w_h3^T + b_h3)        (o3)
    gemm_nt<<<gridH, blk>>>(p_h2, p_s3, w_h3, b_h3, p_out, HH, HH, 3);
    // mu / logstd from out, one batched launch
    gemm_nt_multi<<<gridC2, blk>>>(p_out,
                                   w_mu, b_mu, out_mu,
                                   w_s,  b_s,  out_ls,
                                   w_s,  b_s,  out_ls,   // unused (z<2)
                                   HH, CC, 0);
}